// round 8
// baseline (speedup 1.0000x reference)
#include <cuda_runtime.h>
#include <cuda_fp16.h>
#include <math.h>

#define Bq 4
#define Nq 4096
#define Hq 8
#define Dq 64
#define Mq 64
#define SEG 32
#define BH  (Bq*Hq)
#define P2  72          // smem row pitch in halves (144B: 16B-aligned, ldmatrix conflict-free)

// Scratch (fully written each launch)
__device__ float g_KVp[SEG*BH*Dq*Mq];   // partial KV [seg][bh][d][m]
__device__ float g_Ksp[SEG*BH*Dq];      // partial Ksum
__device__ float g_KV[BH*Dq*Mq];
__device__ float g_Ksum[BH*Dq];

__device__ __forceinline__ float fmap(float x) {
    return x > 0.0f ? x + 1.0f : __expf(x);   // elu(x)+1
}
__device__ __forceinline__ unsigned pack_h2(float lo, float hi) {
    __half2 h = __floats2half2_rn(lo, hi);
    return *reinterpret_cast<unsigned*>(&h);
}
__device__ __forceinline__ void mma_fp16(float4& d,
                                         unsigned a0, unsigned a1, unsigned a2, unsigned a3,
                                         unsigned b0, unsigned b1) {
    asm volatile(
        "mma.sync.aligned.m16n8k16.row.col.f32.f16.f16.f32 "
        "{%0,%1,%2,%3}, {%4,%5,%6,%7}, {%8,%9}, {%0,%1,%2,%3};"
        : "+f"(d.x), "+f"(d.y), "+f"(d.z), "+f"(d.w)
        : "r"(a0), "r"(a1), "r"(a2), "r"(a3), "r"(b0), "r"(b1));
}
__device__ __forceinline__ void ldm_x4t(unsigned& r0, unsigned& r1, unsigned& r2, unsigned& r3,
                                        unsigned addr) {
    asm volatile("ldmatrix.sync.aligned.m8n8.x4.trans.shared.b16 {%0,%1,%2,%3}, [%4];"
        : "=r"(r0), "=r"(r1), "=r"(r2), "=r"(r3) : "r"(addr));
}
__device__ __forceinline__ void ldm_x4(unsigned& r0, unsigned& r1, unsigned& r2, unsigned& r3,
                                       unsigned addr) {
    asm volatile("ldmatrix.sync.aligned.m8n8.x4.shared.b16 {%0,%1,%2,%3}, [%4];"
        : "=r"(r0), "=r"(r1), "=r"(r2), "=r"(r3) : "r"(addr));
}
__device__ __forceinline__ void ldm_x2t(unsigned& r0, unsigned& r1, unsigned addr) {
    asm volatile("ldmatrix.sync.aligned.m8n8.x2.trans.shared.b16 {%0,%1}, [%2];"
        : "=r"(r0), "=r"(r1) : "r"(addr));
}

// ============ pass1: KV_partial[seg][bh] = fmap(K)^T V over this seg's 128 rows ============
// grid (SEG, H, B) = 1024 blocks, 256 thr (8 warps). Output tile 64(d) x 64(m).
// Warp w: d-strip = w&3 (16 d), m j-tiles 4*(w>>2)..+3 (32 m).
// Single 128-row chunk; staging batched for MLP.
__global__ void __launch_bounds__(256) pass1_kernel(const float* __restrict__ Kp,
                                                    const float* __restrict__ Vp) {
    __shared__ __align__(16) __half Ksm[128][P2];
    __shared__ __align__(16) __half Vsm[128][P2];

    const int b = blockIdx.z, h = blockIdx.y, seg = blockIdx.x;
    const int bh = b * Hq + h;
    const int tid = threadIdx.x;
    const int w = tid >> 5, lane = tid & 31;
    const int gid = lane >> 2, tig = lane & 3;
    const int strip = w & 3;          // d-strip (16 d-rows)
    const int jt0 = (w >> 2) * 4;     // first m j-tile (of 4)
    const int n0 = seg * 128;

    const unsigned Kbase = (unsigned)__cvta_generic_to_shared(&Ksm[0][0]);
    const unsigned Vbase = (unsigned)__cvta_generic_to_shared(&Vsm[0][0]);
    const int g = lane >> 3, r = lane & 7;
    // A (trans, x4): row = k0 + (g>=2?8:0) + r ; col = d0 + (g&1?8:0)
    const int arow_off = ((g >> 1) ? 8 : 0) + r;
    const int acol_off = (g & 1) ? 8 : 0;
    // B (trans, x2): row = k0 + (g&1?8:0) + r ; col = m0
    const int brow_off = ((g & 1) ? 8 : 0) + r;

    // ---- staging: 2048 jobs = 128 rows x 16 c4-chunks; 8 iters/thread, batched 4 ----
    #pragma unroll
    for (int bt = 0; bt < 2; bt++) {
        float4 kreg[4], vreg[4];
        int nn[4], cc[4];
        #pragma unroll
        for (int i = 0; i < 4; i++) {
            const int job = (bt * 4 + i) * 256 + tid;
            nn[i] = job >> 4; cc[i] = job & 15;
            const size_t base = ((size_t)(b * Nq + n0 + nn[i]) * Hq + h);
            kreg[i] = *(const float4*)(Kp + base * Dq + cc[i] * 4);
            vreg[i] = *(const float4*)(Vp + base * Mq + cc[i] * 4);
        }
        #pragma unroll
        for (int i = 0; i < 4; i++) {
            uint2 ku, vu;
            ku.x = pack_h2(fmap(kreg[i].x), fmap(kreg[i].y));
            ku.y = pack_h2(fmap(kreg[i].z), fmap(kreg[i].w));
            *(uint2*)&Ksm[nn[i]][cc[i] * 4] = ku;
            vu.x = pack_h2(vreg[i].x, vreg[i].y);
            vu.y = pack_h2(vreg[i].z, vreg[i].w);
            *(uint2*)&Vsm[nn[i]][cc[i] * 4] = vu;
        }
    }
    __syncthreads();

    // Ksum partial (threads 0..63, d = tid)
    if (tid < 64) {
        float s = 0.0f;
        #pragma unroll 8
        for (int n = 0; n < 128; n++) s += __half2float(Ksm[n][tid]);
        g_Ksp[((size_t)seg * BH + bh) * Dq + tid] = s;
    }

    float4 acc[4];
    #pragma unroll
    for (int j = 0; j < 4; j++) acc[j] = make_float4(0.f, 0.f, 0.f, 0.f);

    // MMA mainloop: 8 k-steps of 16 over the 128 staged rows
    const int d0 = 16 * strip;
    #pragma unroll
    for (int ks = 0; ks < 8; ks++) {
        const int k0 = ks * 16;
        unsigned a0, a1, a2, a3;
        const unsigned aaddr = Kbase +
            ((unsigned)((k0 + arow_off) * P2 + d0 + acol_off)) * 2u;
        ldm_x4t(a0, a1, a2, a3, aaddr);
        #pragma unroll
        for (int j = 0; j < 4; j++) {
            const int m0 = 8 * (jt0 + j);
            unsigned b0, b1;
            const unsigned baddr = Vbase +
                ((unsigned)((k0 + brow_off) * P2 + m0)) * 2u;
            ldm_x2t(b0, b1, baddr);
            mma_fp16(acc[j], a0, a1, a2, a3, b0, b1);
        }
    }

    // epilogue: write partial KV (block exclusively owns [seg][bh])
    float* kv = g_KVp + ((size_t)seg * BH + bh) * Dq * Mq;
    const int d = d0 + gid;
    #pragma unroll
    for (int j = 0; j < 4; j++) {
        const int m = 8 * (jt0 + j) + 2 * tig;
        *(float2*)(kv + (size_t)d * Mq + m)       = make_float2(acc[j].x, acc[j].y);
        *(float2*)(kv + (size_t)(d + 8) * Mq + m) = make_float2(acc[j].z, acc[j].w);
    }
}

// ============ reduce: sum SEG partials ============
__global__ void __launch_bounds__(256) reduce_kernel() {
    const int i = blockIdx.x * 256 + threadIdx.x;
    if (i < BH * Dq * Mq) {
        float s = 0.0f;
        #pragma unroll
        for (int sg = 0; sg < SEG; sg++) s += g_KVp[(size_t)sg * BH * Dq * Mq + i];
        g_KV[i] = s;
    }
    if (i < BH * Dq) {
        float s = 0.0f;
        #pragma unroll
        for (int sg = 0; sg < SEG; sg++) s += g_Ksp[sg * BH * Dq + i];
        g_Ksum[i] = s;
    }
}

// ============ pass2: out = Z * fmap(Q) @ KV ============
// grid (32, H, B) = 1024 blocks, 256 thr (8 warps). Tile: 128 n-rows x 64 m.
// Warp w: n-strip = w (rows 16w..16w+15), all 8 m j-tiles.
__global__ void __launch_bounds__(256) pass2_kernel(const float* __restrict__ Qp,
                                                    float* __restrict__ Op) {
    __shared__ __align__(16) __half Qsm[128][P2];   // [n][d]
    __shared__ __align__(16) __half KVsm[64][P2];   // [d][m]
    __shared__ float Zs[128];
    __shared__ float Kss[64];

    const int b = blockIdx.z, h = blockIdx.y;
    const int bh = b * Hq + h;
    const int n0 = blockIdx.x * 128;
    const int tid = threadIdx.x;
    const int w = tid >> 5, lane = tid & 31;
    const int gid = lane >> 2, tig = lane & 3;

    const unsigned Qbase  = (unsigned)__cvta_generic_to_shared(&Qsm[0][0]);
    const unsigned KVbase = (unsigned)__cvta_generic_to_shared(&KVsm[0][0]);
    const int g = lane >> 3, r = lane & 7;
    // A (non-trans, x4): row = nrow0 + (g&1?8:0) + r ; col = k0 + (g>=2?8:0)
    const int arow_off = ((g & 1) ? 8 : 0) + r;
    const int acol_off = (g >> 1) ? 8 : 0;
    // B (trans, x2): row = k0 + (g&1?8:0) + r ; col = m0
    const int brow_off = ((g & 1) ? 8 : 0) + r;

    // ---- staging: KV 1024 jobs (4 iters), Q 2048 jobs (8 iters), batched ----
    const float* kvg = g_KV + (size_t)bh * Dq * Mq;
    {
        float4 t[4];
        int rr[4], cc[4];
        #pragma unroll
        for (int i = 0; i < 4; i++) {
            const int job = i * 256 + tid;
            rr[i] = job >> 4; cc[i] = job & 15;
            t[i] = *(const float4*)(kvg + (size_t)rr[i] * Mq + cc[i] * 4);
        }
        #pragma unroll
        for (int i = 0; i < 4; i++) {
            uint2 tu;
            tu.x = pack_h2(t[i].x, t[i].y);
            tu.y = pack_h2(t[i].z, t[i].w);
            *(uint2*)&KVsm[rr[i]][cc[i] * 4] = tu;
        }
    }
    #pragma unroll
    for (int bt = 0; bt < 2; bt++) {
        float4 q[4];
        int rr[4], cc[4];
        #pragma unroll
        for (int i = 0; i < 4; i++) {
            const int job = (bt * 4 + i) * 256 + tid;
            rr[i] = job >> 4; cc[i] = job & 15;
            q[i] = *(const float4*)(Qp + ((size_t)(b * Nq + n0 + rr[i]) * Hq + h) * Dq + cc[i] * 4);
        }
        #pragma unroll
        for (int i = 0; i < 4; i++) {
            uint2 qu;
            qu.x = pack_h2(fmap(q[i].x), fmap(q[i].y));
            qu.y = pack_h2(fmap(q[i].z), fmap(q[i].w));
            *(uint2*)&Qsm[rr[i]][cc[i] * 4] = qu;
        }
    }
    if (tid < 64) Kss[tid] = g_Ksum[bh * Dq + tid];
    __syncthreads();

    // Z per row (128 rows, threads 0..127)
    if (tid < 128) {
        float s = 0.0f;
        #pragma unroll 8
        for (int d = 0; d < Dq; d++) s += __half2float(Qsm[tid][d]) * Kss[d];
        Zs[tid] = 1.0f / (s + 1e-6f);
    }
    __syncthreads();

    float4 acc[8];
    #pragma unroll
    for (int j = 0; j < 8; j++) acc[j] = make_float4(0.f, 0.f, 0.f, 0.f);

    const int nr0 = 16 * w;
    #pragma unroll
    for (int ks = 0; ks < 4; ks++) {
        const int k0 = ks * 16;
        unsigned a0, a1, a2, a3;
        const unsigned aaddr = Qbase +
            ((unsigned)((nr0 + arow_off) * P2 + k0 + acol_off)) * 2u;
        ldm_x4(a0, a1, a2, a3, aaddr);
        #pragma unroll
        for (int j = 0; j < 8; j++) {
            const int m0 = 8 * j;
            unsigned b0, b1;
            const unsigned baddr = KVbase +
                ((unsigned)((k0 + brow_off) * P2 + m0)) * 2u;
            ldm_x2t(b0, b1, baddr);
            mma_fp16(acc[j], a0, a1, a2, a3, b0, b1);
        }
    }

    // epilogue: scale by Z, store
    const int row = nr0 + gid;
    const float z0 = Zs[row], z1 = Zs[row + 8];
    float* op0 = Op + ((size_t)(b * Nq + n0 + row) * Hq + h) * Mq;
    float* op1 = op0 + (size_t)8 * Hq * Mq;
    #pragma unroll
    for (int j = 0; j < 8; j++) {
        const int m = 8 * j + 2 * tig;
        *(float2*)(op0 + m) = make_float2(acc[j].x * z0, acc[j].y * z0);
        *(float2*)(op1 + m) = make_float2(acc[j].z * z1, acc[j].w * z1);
    }
}

extern "C" void kernel_launch(void* const* d_in, const int* in_sizes, int n_in,
                              void* d_out, int out_size) {
    const float* Q = (const float*)d_in[0];
    const float* K = (const float*)d_in[1];
    const float* V = (const float*)d_in[2];
    float* out = (float*)d_out;

    pass1_kernel<<<dim3(SEG, Hq, Bq), 256>>>(K, V);
    reduce_kernel<<<512, 256>>>();
    pass2_kernel<<<dim3(32, Hq, Bq), 256>>>(Q, out);
}

// round 9
// speedup vs baseline: 1.0457x; 1.0457x over previous
#include <cuda_runtime.h>
#include <cuda_fp16.h>
#include <math.h>

#define Bq 4
#define Nq 4096
#define Hq 8
#define Dq 64
#define Mq 64
#define SEG 32
#define BH  (Bq*Hq)
#define P2  72          // smem row pitch in halves (144B: 16B-aligned, ldmatrix conflict-free)
#define ONESH2 0x3C003C00u   // half2(1.0, 1.0)

// Scratch (fully written each launch)
__device__ float g_KVp[SEG*BH*Dq*Mq];   // partial KV [seg][bh][d][m]
__device__ float g_Ksp[SEG*BH*Dq];      // partial Ksum
__device__ float g_KV[BH*Dq*Mq];
__device__ float g_Ksum[BH*Dq];

__device__ __forceinline__ float fmap(float x) {
    return x > 0.0f ? x + 1.0f : __expf(x);   // elu(x)+1
}
__device__ __forceinline__ unsigned pack_h2(float lo, float hi) {
    __half2 h = __floats2half2_rn(lo, hi);
    return *reinterpret_cast<unsigned*>(&h);
}
__device__ __forceinline__ void mma_fp16(float4& d,
                                         unsigned a0, unsigned a1, unsigned a2, unsigned a3,
                                         unsigned b0, unsigned b1) {
    asm volatile(
        "mma.sync.aligned.m16n8k16.row.col.f32.f16.f16.f32 "
        "{%0,%1,%2,%3}, {%4,%5,%6,%7}, {%8,%9}, {%0,%1,%2,%3};"
        : "+f"(d.x), "+f"(d.y), "+f"(d.z), "+f"(d.w)
        : "r"(a0), "r"(a1), "r"(a2), "r"(a3), "r"(b0), "r"(b1));
}
__device__ __forceinline__ void ldm_x4t(unsigned& r0, unsigned& r1, unsigned& r2, unsigned& r3,
                                        unsigned addr) {
    asm volatile("ldmatrix.sync.aligned.m8n8.x4.trans.shared.b16 {%0,%1,%2,%3}, [%4];"
        : "=r"(r0), "=r"(r1), "=r"(r2), "=r"(r3) : "r"(addr));
}
__device__ __forceinline__ void ldm_x4(unsigned& r0, unsigned& r1, unsigned& r2, unsigned& r3,
                                       unsigned addr) {
    asm volatile("ldmatrix.sync.aligned.m8n8.x4.shared.b16 {%0,%1,%2,%3}, [%4];"
        : "=r"(r0), "=r"(r1), "=r"(r2), "=r"(r3) : "r"(addr));
}
__device__ __forceinline__ void ldm_x2t(unsigned& r0, unsigned& r1, unsigned addr) {
    asm volatile("ldmatrix.sync.aligned.m8n8.x2.trans.shared.b16 {%0,%1}, [%2];"
        : "=r"(r0), "=r"(r1) : "r"(addr));
}

// ============ pass1: KV_partial[seg][bh] = fmap(K)^T V over this seg's 128 rows ============
// grid (SEG, H, B) = 1024 blocks, 256 thr (8 warps). Output tile 64(d) x 64(m).
// Warp w: d-strip = w&3 (16 d), m j-tiles 4*(w>>2)..+3 (32 m).
// Ksum folded into MMA with B = ones (warps 0-3 only).
__global__ void __launch_bounds__(256) pass1_kernel(const float* __restrict__ Kp,
                                                    const float* __restrict__ Vp) {
    __shared__ __align__(16) __half Ksm[128][P2];
    __shared__ __align__(16) __half Vsm[128][P2];

    const int b = blockIdx.z, h = blockIdx.y, seg = blockIdx.x;
    const int bh = b * Hq + h;
    const int tid = threadIdx.x;
    const int w = tid >> 5, lane = tid & 31;
    const int gid = lane >> 2, tig = lane & 3;
    const int strip = w & 3;          // d-strip (16 d-rows)
    const int jt0 = (w >> 2) * 4;     // first m j-tile (of 4)
    const int n0 = seg * 128;

    const unsigned Kbase = (unsigned)__cvta_generic_to_shared(&Ksm[0][0]);
    const unsigned Vbase = (unsigned)__cvta_generic_to_shared(&Vsm[0][0]);
    const int g = lane >> 3, r = lane & 7;
    const int arow_off = ((g >> 1) ? 8 : 0) + r;   // A (trans, x4)
    const int acol_off = (g & 1) ? 8 : 0;
    const int brow_off = ((g & 1) ? 8 : 0) + r;    // B (trans, x2)

    // base pointers hoisted: row stride is Hq*Dq = Hq*Mq = 512 floats
    const float* kp = Kp + ((size_t)(b * Nq + n0) * Hq + h) * Dq;
    const float* vp = Vp + ((size_t)(b * Nq + n0) * Hq + h) * Mq;
    const int nrow = tid >> 4, c4 = tid & 15;

    // staging: 8 iters, interleaved LDG->convert->STS (immediate offsets)
    #pragma unroll
    for (int it = 0; it < 8; it++) {
        const int n = it * 16 + nrow;
        const float4 k4 = *(const float4*)(kp + (size_t)n * 512 + c4 * 4);
        const float4 v4 = *(const float4*)(vp + (size_t)n * 512 + c4 * 4);
        uint2 ku, vu;
        ku.x = pack_h2(fmap(k4.x), fmap(k4.y));
        ku.y = pack_h2(fmap(k4.z), fmap(k4.w));
        *(uint2*)&Ksm[n][c4 * 4] = ku;
        vu.x = pack_h2(v4.x, v4.y);
        vu.y = pack_h2(v4.z, v4.w);
        *(uint2*)&Vsm[n][c4 * 4] = vu;
    }
    __syncthreads();

    float4 acc[4];
    #pragma unroll
    for (int j = 0; j < 4; j++) acc[j] = make_float4(0.f, 0.f, 0.f, 0.f);
    float4 accK = make_float4(0.f, 0.f, 0.f, 0.f);   // Ksum accumulator (warps 0-3)

    const int d0 = 16 * strip;
    #pragma unroll
    for (int ks = 0; ks < 8; ks++) {
        const int k0 = ks * 16;
        unsigned a0, a1, a2, a3;
        const unsigned aaddr = Kbase +
            ((unsigned)((k0 + arow_off) * P2 + d0 + acol_off)) * 2u;
        ldm_x4t(a0, a1, a2, a3, aaddr);
        if (w < 4)   // Ksum = K'^T @ ones
            mma_fp16(accK, a0, a1, a2, a3, ONESH2, ONESH2);
        #pragma unroll
        for (int j = 0; j < 4; j++) {
            const int m0 = 8 * (jt0 + j);
            unsigned b0, b1;
            const unsigned baddr = Vbase +
                ((unsigned)((k0 + brow_off) * P2 + m0)) * 2u;
            ldm_x2t(b0, b1, baddr);
            mma_fp16(acc[j], a0, a1, a2, a3, b0, b1);
        }
    }

    // epilogue: write partial KV (block exclusively owns [seg][bh])
    float* kv = g_KVp + ((size_t)seg * BH + bh) * Dq * Mq;
    const int d = d0 + gid;
    #pragma unroll
    for (int j = 0; j < 4; j++) {
        const int m = 8 * (jt0 + j) + 2 * tig;
        *(float2*)(kv + (size_t)d * Mq + m)       = make_float2(acc[j].x, acc[j].y);
        *(float2*)(kv + (size_t)(d + 8) * Mq + m) = make_float2(acc[j].z, acc[j].w);
    }
    if (w < 4 && tig == 0) {   // col 0 of the ones-MMA = Ksum strip
        float* kss = g_Ksp + ((size_t)seg * BH + bh) * Dq;
        kss[d0 + gid]     = accK.x;
        kss[d0 + gid + 8] = accK.z;
    }
}

// ============ reduce: sum SEG partials ============
__global__ void __launch_bounds__(256) reduce_kernel() {
    const int i = blockIdx.x * 256 + threadIdx.x;
    if (i < BH * Dq * Mq) {
        float s = 0.0f;
        #pragma unroll
        for (int sg = 0; sg < SEG; sg++) s += g_KVp[(size_t)sg * BH * Dq * Mq + i];
        g_KV[i] = s;
    }
    if (i < BH * Dq) {
        float s = 0.0f;
        #pragma unroll
        for (int sg = 0; sg < SEG; sg++) s += g_Ksp[sg * BH * Dq + i];
        g_Ksum[i] = s;
    }
}

// ============ pass2: out = Z * fmap(Q) @ KV ============
// grid (32, H, B) = 1024 blocks, 256 thr (8 warps). Tile: 128 n-rows x 64 m.
// Warp w: n-strip = w (rows 16w..16w+15), all 8 m j-tiles.
// Z folded into MMA: extra j-tile with B = Ksum (broadcast over n); every lane
// then holds denom(gid)=.x and denom(gid+8)=.z directly — no scalar Z phase.
__global__ void __launch_bounds__(256) pass2_kernel(const float* __restrict__ Qp,
                                                    float* __restrict__ Op) {
    __shared__ __align__(16) __half Qsm[128][P2];   // [n][d]
    __shared__ __align__(16) __half KVsm[64][P2];   // [d][m]
    __shared__ float Kss[64];

    const int b = blockIdx.z, h = blockIdx.y;
    const int bh = b * Hq + h;
    const int n0 = blockIdx.x * 128;
    const int tid = threadIdx.x;
    const int w = tid >> 5, lane = tid & 31;
    const int gid = lane >> 2, tig = lane & 3;

    const unsigned Qbase  = (unsigned)__cvta_generic_to_shared(&Qsm[0][0]);
    const unsigned KVbase = (unsigned)__cvta_generic_to_shared(&KVsm[0][0]);
    const int g = lane >> 3, r = lane & 7;
    const int arow_off = ((g & 1) ? 8 : 0) + r;    // A (non-trans, x4)
    const int acol_off = (g >> 1) ? 8 : 0;
    const int brow_off = ((g & 1) ? 8 : 0) + r;    // B (trans, x2)

    // staging (base pointers hoisted, immediate offsets)
    const float* kvg = g_KV + (size_t)bh * Dq * Mq;
    const float* qp  = Qp + ((size_t)(b * Nq + n0) * Hq + h) * Dq;
    const int nrow = tid >> 4, c4 = tid & 15;

    #pragma unroll
    for (int it = 0; it < 4; it++) {
        const int rr = it * 16 + nrow;
        const float4 t = *(const float4*)(kvg + (size_t)rr * Mq + c4 * 4);
        uint2 tu;
        tu.x = pack_h2(t.x, t.y);
        tu.y = pack_h2(t.z, t.w);
        *(uint2*)&KVsm[rr][c4 * 4] = tu;
    }
    #pragma unroll
    for (int it = 0; it < 8; it++) {
        const int rr = it * 16 + nrow;
        const float4 q = *(const float4*)(qp + (size_t)rr * 512 + c4 * 4);
        uint2 qu;
        qu.x = pack_h2(fmap(q.x), fmap(q.y));
        qu.y = pack_h2(fmap(q.z), fmap(q.w));
        *(uint2*)&Qsm[rr][c4 * 4] = qu;
    }
    if (tid < 64) Kss[tid] = g_Ksum[bh * Dq + tid];
    __syncthreads();

    float4 acc[8];
    #pragma unroll
    for (int j = 0; j < 8; j++) acc[j] = make_float4(0.f, 0.f, 0.f, 0.f);
    float4 accZ = make_float4(0.f, 0.f, 0.f, 0.f);

    const int nr0 = 16 * w;
    #pragma unroll
    for (int ks = 0; ks < 4; ks++) {
        const int k0 = ks * 16;
        unsigned a0, a1, a2, a3;
        const unsigned aaddr = Qbase +
            ((unsigned)((nr0 + arow_off) * P2 + k0 + acol_off)) * 2u;
        ldm_x4(a0, a1, a2, a3, aaddr);
        // Z fragment: B[k][n] = Kss[k] broadcast over n
        const unsigned zb0 = pack_h2(Kss[k0 + 2 * tig],     Kss[k0 + 2 * tig + 1]);
        const unsigned zb1 = pack_h2(Kss[k0 + 2 * tig + 8], Kss[k0 + 2 * tig + 9]);
        mma_fp16(accZ, a0, a1, a2, a3, zb0, zb1);
        #pragma unroll
        for (int j = 0; j < 8; j++) {
            const int m0 = 8 * j;
            unsigned b0, b1;
            const unsigned baddr = KVbase +
                ((unsigned)((k0 + brow_off) * P2 + m0)) * 2u;
            ldm_x2t(b0, b1, baddr);
            mma_fp16(acc[j], a0, a1, a2, a3, b0, b1);
        }
    }

    // per-lane normalizers from the Z-tile
    const float z0 = 1.0f / (accZ.x + 1e-6f);
    const float z1 = 1.0f / (accZ.z + 1e-6f);

    // epilogue: scale by Z, store
    const int row = nr0 + gid;
    float* op0 = Op + ((size_t)(b * Nq + n0 + row) * Hq + h) * Mq;
    float* op1 = op0 + (size_t)8 * Hq * Mq;
    #pragma unroll
    for (int j = 0; j < 8; j++) {
        const int m = 8 * j + 2 * tig;
        *(float2*)(op0 + m) = make_float2(acc[j].x * z0, acc[j].y * z0);
        *(float2*)(op1 + m) = make_float2(acc[j].z * z1, acc[j].w * z1);
    }
}

extern "C" void kernel_launch(void* const* d_in, const int* in_sizes, int n_in,
                              void* d_out, int out_size) {
    const float* Q = (const float*)d_in[0];
    const float* K = (const float*)d_in[1];
    const float* V = (const float*)d_in[2];
    float* out = (float*)d_out;

    pass1_kernel<<<dim3(SEG, Hq, Bq), 256>>>(K, V);
    reduce_kernel<<<512, 256>>>();
    pass2_kernel<<<dim3(32, Hq, Bq), 256>>>(Q, out);
}

// round 10
// speedup vs baseline: 1.0941x; 1.0463x over previous
#include <cuda_runtime.h>
#include <cuda_fp16.h>
#include <math.h>

#define Bq 4
#define Nq 4096
#define Hq 8
#define Dq 64
#define Mq 64
#define SEG 16
#define BH  (Bq*Hq)
#define P2  72          // smem row pitch in halves (144B: 16B-aligned, ldmatrix conflict-free)
#define ONESH2 0x3C003C00u   // half2(1.0, 1.0)

// Scratch (fully written each launch)
__device__ float g_KVp[SEG*BH*Dq*Mq];   // partial KV [seg][bh][d][m]
__device__ float g_Ksp[SEG*BH*Dq];      // partial Ksum
__device__ float g_KV[BH*Dq*Mq];
__device__ float g_Ksum[BH*Dq];

__device__ __forceinline__ float fmap(float x) {
    return x > 0.0f ? x + 1.0f : __expf(x);   // elu(x)+1
}
__device__ __forceinline__ unsigned pack_h2(float lo, float hi) {
    __half2 h = __floats2half2_rn(lo, hi);
    return *reinterpret_cast<unsigned*>(&h);
}
__device__ __forceinline__ void mma_fp16(float4& d,
                                         unsigned a0, unsigned a1, unsigned a2, unsigned a3,
                                         unsigned b0, unsigned b1) {
    asm volatile(
        "mma.sync.aligned.m16n8k16.row.col.f32.f16.f16.f32 "
        "{%0,%1,%2,%3}, {%4,%5,%6,%7}, {%8,%9}, {%0,%1,%2,%3};"
        : "+f"(d.x), "+f"(d.y), "+f"(d.z), "+f"(d.w)
        : "r"(a0), "r"(a1), "r"(a2), "r"(a3), "r"(b0), "r"(b1));
}
__device__ __forceinline__ void ldm_x4t(unsigned& r0, unsigned& r1, unsigned& r2, unsigned& r3,
                                        unsigned addr) {
    asm volatile("ldmatrix.sync.aligned.m8n8.x4.trans.shared.b16 {%0,%1,%2,%3}, [%4];"
        : "=r"(r0), "=r"(r1), "=r"(r2), "=r"(r3) : "r"(addr));
}
__device__ __forceinline__ void ldm_x4(unsigned& r0, unsigned& r1, unsigned& r2, unsigned& r3,
                                       unsigned addr) {
    asm volatile("ldmatrix.sync.aligned.m8n8.x4.shared.b16 {%0,%1,%2,%3}, [%4];"
        : "=r"(r0), "=r"(r1), "=r"(r2), "=r"(r3) : "r"(addr));
}
__device__ __forceinline__ void ldm_x2t(unsigned& r0, unsigned& r1, unsigned addr) {
    asm volatile("ldmatrix.sync.aligned.m8n8.x2.trans.shared.b16 {%0,%1}, [%2];"
        : "=r"(r0), "=r"(r1) : "r"(addr));
}

// ============ pass1: KV_partial[seg][bh] = fmap(K)^T V over this seg's 256 rows ============
// grid (SEG, H, B) = 512 blocks, 256 thr (8 warps). Output tile 64(d) x 64(m).
// 4 chunks of 64 rows, double-buffered smem, register-prefetch pipeline:
//   prefetch(c+1) overlaps MMA(c) -> DRAM stays busy during tensor phases.
// Warp w: d-strip = w&3 (16 d), m j-tiles 4*(w>>2)..+3 (32 m).
// Ksum folded into MMA with B = ones (warps 0-3 only).
__global__ void __launch_bounds__(256) pass1_kernel(const float* __restrict__ Kp,
                                                    const float* __restrict__ Vp) {
    __shared__ __align__(16) __half Ksm[2][64][P2];
    __shared__ __align__(16) __half Vsm[2][64][P2];

    const int b = blockIdx.z, h = blockIdx.y, seg = blockIdx.x;
    const int bh = b * Hq + h;
    const int tid = threadIdx.x;
    const int w = tid >> 5, lane = tid & 31;
    const int gid = lane >> 2, tig = lane & 3;
    const int strip = w & 3;          // d-strip (16 d-rows)
    const int jt0 = (w >> 2) * 4;     // first m j-tile (of 4)
    const int n0 = seg * 256;

    const int g = lane >> 3, r = lane & 7;
    const int arow_off = ((g >> 1) ? 8 : 0) + r;   // A (trans, x4)
    const int acol_off = (g & 1) ? 8 : 0;
    const int brow_off = ((g & 1) ? 8 : 0) + r;    // B (trans, x2)

    // hoisted base pointers; row stride = Hq*Dq = Hq*Mq = 512 floats
    const float* kp = Kp + ((size_t)(b * Nq + n0) * Hq + h) * Dq;
    const float* vp = Vp + ((size_t)(b * Nq + n0) * Hq + h) * Mq;
    const int nrow = tid >> 4, c4 = tid & 15;   // 4 staging iters/chunk: n = it*16+nrow

    float4 kreg[4], vreg[4];
    // prefetch chunk 0
    #pragma unroll
    for (int i = 0; i < 4; i++) {
        const int n = i * 16 + nrow;
        kreg[i] = *(const float4*)(kp + (size_t)n * 512 + c4 * 4);
        vreg[i] = *(const float4*)(vp + (size_t)n * 512 + c4 * 4);
    }

    float4 acc[4];
    #pragma unroll
    for (int j = 0; j < 4; j++) acc[j] = make_float4(0.f, 0.f, 0.f, 0.f);
    float4 accK = make_float4(0.f, 0.f, 0.f, 0.f);   // Ksum accumulator (warps 0-3)

    const int d0 = 16 * strip;
    #pragma unroll
    for (int c = 0; c < 4; c++) {
        const int buf = c & 1;
        // convert + STS current chunk from regs
        #pragma unroll
        for (int i = 0; i < 4; i++) {
            const int n = i * 16 + nrow;
            uint2 ku, vu;
            ku.x = pack_h2(fmap(kreg[i].x), fmap(kreg[i].y));
            ku.y = pack_h2(fmap(kreg[i].z), fmap(kreg[i].w));
            *(uint2*)&Ksm[buf][n][c4 * 4] = ku;
            vu.x = pack_h2(vreg[i].x, vreg[i].y);
            vu.y = pack_h2(vreg[i].z, vreg[i].w);
            *(uint2*)&Vsm[buf][n][c4 * 4] = vu;
        }
        // prefetch next chunk — LDG in flight during the MMA below
        if (c < 3) {
            #pragma unroll
            for (int i = 0; i < 4; i++) {
                const int n = (c + 1) * 64 + i * 16 + nrow;
                kreg[i] = *(const float4*)(kp + (size_t)n * 512 + c4 * 4);
                vreg[i] = *(const float4*)(vp + (size_t)n * 512 + c4 * 4);
            }
        }
        __syncthreads();

        const unsigned Kbase = (unsigned)__cvta_generic_to_shared(&Ksm[buf][0][0]);
        const unsigned Vbase = (unsigned)__cvta_generic_to_shared(&Vsm[buf][0][0]);
        #pragma unroll
        for (int ks = 0; ks < 4; ks++) {
            const int k0 = ks * 16;
            unsigned a0, a1, a2, a3;
            const unsigned aaddr = Kbase +
                ((unsigned)((k0 + arow_off) * P2 + d0 + acol_off)) * 2u;
            ldm_x4t(a0, a1, a2, a3, aaddr);
            if (w < 4)   // Ksum = K'^T @ ones
                mma_fp16(accK, a0, a1, a2, a3, ONESH2, ONESH2);
            #pragma unroll
            for (int j = 0; j < 4; j++) {
                const int m0 = 8 * (jt0 + j);
                unsigned b0, b1;
                const unsigned baddr = Vbase +
                    ((unsigned)((k0 + brow_off) * P2 + m0)) * 2u;
                ldm_x2t(b0, b1, baddr);
                mma_fp16(acc[j], a0, a1, a2, a3, b0, b1);
            }
        }
    }

    // epilogue: write partial KV (block exclusively owns [seg][bh])
    float* kv = g_KVp + ((size_t)seg * BH + bh) * Dq * Mq;
    const int d = d0 + gid;
    #pragma unroll
    for (int j = 0; j < 4; j++) {
        const int m = 8 * (jt0 + j) + 2 * tig;
        *(float2*)(kv + (size_t)d * Mq + m)       = make_float2(acc[j].x, acc[j].y);
        *(float2*)(kv + (size_t)(d + 8) * Mq + m) = make_float2(acc[j].z, acc[j].w);
    }
    if (w < 4 && tig == 0) {   // col 0 of the ones-MMA = Ksum strip
        float* kss = g_Ksp + ((size_t)seg * BH + bh) * Dq;
        kss[d0 + gid]     = accK.x;
        kss[d0 + gid + 8] = accK.z;
    }
}

// ============ reduce: sum SEG partials ============
__global__ void __launch_bounds__(256) reduce_kernel() {
    const int i = blockIdx.x * 256 + threadIdx.x;
    if (i < BH * Dq * Mq) {
        float s = 0.0f;
        #pragma unroll
        for (int sg = 0; sg < SEG; sg++) s += g_KVp[(size_t)sg * BH * Dq * Mq + i];
        g_KV[i] = s;
    }
    if (i < BH * Dq) {
        float s = 0.0f;
        #pragma unroll
        for (int sg = 0; sg < SEG; sg++) s += g_Ksp[sg * BH * Dq + i];
        g_Ksum[i] = s;
    }
}

// ============ pass2: out = Z * fmap(Q) @ KV ============
// grid (32, H, B) = 1024 blocks, 256 thr (8 warps). 128 n-rows as 2 chunks of 64,
// double-buffered Q tiles with register-prefetch overlap; per-chunk epilogue.
// Warp w (per chunk): n-strip = w&3 (16 rows), m j-tiles 4*(w>>2)..+3.
// Z folded into MMA with B = Ksum fragments (computed once).
__global__ void __launch_bounds__(256) pass2_kernel(const float* __restrict__ Qp,
                                                    float* __restrict__ Op) {
    __shared__ __align__(16) __half Qsm[2][64][P2];  // [buf][n][d]
    __shared__ __align__(16) __half KVsm[64][P2];    // [d][m]
    __shared__ float Kss[64];

    const int b = blockIdx.z, h = blockIdx.y;
    const int bh = b * Hq + h;
    const int n0 = blockIdx.x * 128;
    const int tid = threadIdx.x;
    const int w = tid >> 5, lane = tid & 31;
    const int gid = lane >> 2, tig = lane & 3;
    const int strip = w & 3;
    const int jt0 = (w >> 2) * 4;

    const unsigned KVbase = (unsigned)__cvta_generic_to_shared(&KVsm[0][0]);
    const int g = lane >> 3, r = lane & 7;
    const int arow_off = ((g & 1) ? 8 : 0) + r;    // A (non-trans, x4)
    const int acol_off = (g >> 1) ? 8 : 0;
    const int brow_off = ((g & 1) ? 8 : 0) + r;    // B (trans, x2)

    const float* kvg = g_KV + (size_t)bh * Dq * Mq;
    const float* qp  = Qp + ((size_t)(b * Nq + n0) * Hq + h) * Dq;
    const int nrow = tid >> 4, c4 = tid & 15;

    // prefetch Q chunk 0 (issued first for MLP)
    float4 qreg[4];
    #pragma unroll
    for (int i = 0; i < 4; i++) {
        const int n = i * 16 + nrow;
        qreg[i] = *(const float4*)(qp + (size_t)n * 512 + c4 * 4);
    }
    // stage KV + Ksum
    #pragma unroll
    for (int it = 0; it < 4; it++) {
        const int rr = it * 16 + nrow;
        const float4 t = *(const float4*)(kvg + (size_t)rr * Mq + c4 * 4);
        uint2 tu;
        tu.x = pack_h2(t.x, t.y);
        tu.y = pack_h2(t.z, t.w);
        *(uint2*)&KVsm[rr][c4 * 4] = tu;
    }
    if (tid < 64) Kss[tid] = g_Ksum[bh * Dq + tid];
    __syncthreads();

    // Z fragments from Ksum (constant across chunks)
    unsigned zb0[4], zb1[4];
    #pragma unroll
    for (int ks = 0; ks < 4; ks++) {
        const int k0 = ks * 16;
        zb0[ks] = pack_h2(Kss[k0 + 2 * tig],     Kss[k0 + 2 * tig + 1]);
        zb1[ks] = pack_h2(Kss[k0 + 2 * tig + 8], Kss[k0 + 2 * tig + 9]);
    }

    #pragma unroll
    for (int c = 0; c < 2; c++) {
        const int buf = c;   // 2 chunks, 2 buffers: no WAR reuse
        // STS current Q chunk
        #pragma unroll
        for (int i = 0; i < 4; i++) {
            const int n = i * 16 + nrow;
            uint2 qu;
            qu.x = pack_h2(fmap(qreg[i].x), fmap(qreg[i].y));
            qu.y = pack_h2(fmap(qreg[i].z), fmap(qreg[i].w));
            *(uint2*)&Qsm[buf][n][c4 * 4] = qu;
        }
        // prefetch chunk 1 while chunk 0's MMA runs
        if (c == 0) {
            #pragma unroll
            for (int i = 0; i < 4; i++) {
                const int n = 64 + i * 16 + nrow;
                qreg[i] = *(const float4*)(qp + (size_t)n * 512 + c4 * 4);
            }
        }
        __syncthreads();

        float4 acc[4];
        #pragma unroll
        for (int j = 0; j < 4; j++) acc[j] = make_float4(0.f, 0.f, 0.f, 0.f);
        float4 accZ = make_float4(0.f, 0.f, 0.f, 0.f);

        const unsigned Qbase = (unsigned)__cvta_generic_to_shared(&Qsm[buf][0][0]);
        const int nr0 = 16 * strip;
        #pragma unroll
        for (int ks = 0; ks < 4; ks++) {
            const int k0 = ks * 16;
            unsigned a0, a1, a2, a3;
            const unsigned aaddr = Qbase +
                ((unsigned)((nr0 + arow_off) * P2 + k0 + acol_off)) * 2u;
            ldm_x4(a0, a1, a2, a3, aaddr);
            mma_fp16(accZ, a0, a1, a2, a3, zb0[ks], zb1[ks]);
            #pragma unroll
            for (int j = 0; j < 4; j++) {
                const int m0 = 8 * (jt0 + j);
                unsigned b0, b1;
                const unsigned baddr = KVbase +
                    ((unsigned)((k0 + brow_off) * P2 + m0)) * 2u;
                ldm_x2t(b0, b1, baddr);
                mma_fp16(acc[j], a0, a1, a2, a3, b0, b1);
            }
        }

        // per-lane normalizers + store for this chunk
        const float z0 = 1.0f / (accZ.x + 1e-6f);
        const float z1 = 1.0f / (accZ.z + 1e-6f);
        const int row = c * 64 + nr0 + gid;
        float* op0 = Op + ((size_t)(b * Nq + n0 + row) * Hq + h) * Mq;
        float* op1 = op0 + (size_t)8 * Hq * Mq;
        #pragma unroll
        for (int j = 0; j < 4; j++) {
            const int m = 8 * (jt0 + j) + 2 * tig;
            *(float2*)(op0 + m) = make_float2(acc[j].x * z0, acc[j].y * z0);
            *(float2*)(op1 + m) = make_float2(acc[j].z * z1, acc[j].w * z1);
        }
    }
}

extern "C" void kernel_launch(void* const* d_in, const int* in_sizes, int n_in,
                              void* d_out, int out_size) {
    const float* Q = (const float*)d_in[0];
    const float* K = (const float*)d_in[1];
    const float* V = (const float*)d_in[2];
    float* out = (float*)d_out;

    pass1_kernel<<<dim3(SEG, Hq, Bq), 256>>>(K, V);
    reduce_kernel<<<512, 256>>>();
    pass2_kernel<<<dim3(32, Hq, Bq), 256>>>(Q, out);
}

// round 11
// speedup vs baseline: 1.1138x; 1.0180x over previous
#include <cuda_runtime.h>
#include <cuda_fp16.h>
#include <math.h>

#define Bq 4
#define Nq 4096
#define Hq 8
#define Dq 64
#define Mq 64
#define SEG 32
#define BH  (Bq*Hq)
#define P2  72          // smem row pitch in halves (144B: 16B-aligned, ldmatrix conflict-free)
#define ONESH2 0x3C003C00u   // half2(1.0, 1.0)

// Scratch (fully written each launch)
__device__ float g_KVp[SEG*BH*Dq*Mq];   // partial KV [seg][bh][d][m]
__device__ float g_Ksp[SEG*BH*Dq];      // partial Ksum
__device__ float g_KV[BH*Dq*Mq];
__device__ float g_Ksum[BH*Dq];

__device__ __forceinline__ float fmap(float x) {
    return x > 0.0f ? x + 1.0f : __expf(x);   // elu(x)+1
}
__device__ __forceinline__ unsigned pack_h2(float lo, float hi) {
    __half2 h = __floats2half2_rn(lo, hi);
    return *reinterpret_cast<unsigned*>(&h);
}
__device__ __forceinline__ void mma_fp16(float4& d,
                                         unsigned a0, unsigned a1, unsigned a2, unsigned a3,
                                         unsigned b0, unsigned b1) {
    asm volatile(
        "mma.sync.aligned.m16n8k16.row.col.f32.f16.f16.f32 "
        "{%0,%1,%2,%3}, {%4,%5,%6,%7}, {%8,%9}, {%0,%1,%2,%3};"
        : "+f"(d.x), "+f"(d.y), "+f"(d.z), "+f"(d.w)
        : "r"(a0), "r"(a1), "r"(a2), "r"(a3), "r"(b0), "r"(b1));
}
__device__ __forceinline__ void ldm_x4t(unsigned& r0, unsigned& r1, unsigned& r2, unsigned& r3,
                                        unsigned addr) {
    asm volatile("ldmatrix.sync.aligned.m8n8.x4.trans.shared.b16 {%0,%1,%2,%3}, [%4];"
        : "=r"(r0), "=r"(r1), "=r"(r2), "=r"(r3) : "r"(addr));
}
__device__ __forceinline__ void ldm_x4(unsigned& r0, unsigned& r1, unsigned& r2, unsigned& r3,
                                       unsigned addr) {
    asm volatile("ldmatrix.sync.aligned.m8n8.x4.shared.b16 {%0,%1,%2,%3}, [%4];"
        : "=r"(r0), "=r"(r1), "=r"(r2), "=r"(r3) : "r"(addr));
}
__device__ __forceinline__ void ldm_x2t(unsigned& r0, unsigned& r1, unsigned addr) {
    asm volatile("ldmatrix.sync.aligned.m8n8.x2.trans.shared.b16 {%0,%1}, [%2];"
        : "=r"(r0), "=r"(r1) : "r"(addr));
}

// ============ pass1: KV_partial[seg][bh] = fmap(K)^T V over this seg's 128 rows ============
// grid (SEG, H, B) = 1024 blocks, 256 thr (8 warps), min 4 blocks/SM (regs capped 64).
// 2 chunks of 64 rows, double-buffered smem, register-prefetch pipeline.
// Warp w: d-strip = w&3 (16 d), m j-tiles 4*(w>>2)..+3 (32 m).
// Ksum folded into MMA with B = ones (warps 0-3 only).
__global__ void __launch_bounds__(256, 4) pass1_kernel(const float* __restrict__ Kp,
                                                       const float* __restrict__ Vp) {
    __shared__ __align__(16) __half Ksm[2][64][P2];
    __shared__ __align__(16) __half Vsm[2][64][P2];

    const int b = blockIdx.z, h = blockIdx.y, seg = blockIdx.x;
    const int bh = b * Hq + h;
    const int tid = threadIdx.x;
    const int w = tid >> 5, lane = tid & 31;
    const int gid = lane >> 2, tig = lane & 3;
    const int strip = w & 3;          // d-strip (16 d-rows)
    const int jt0 = (w >> 2) * 4;     // first m j-tile (of 4)
    const int n0 = seg * 128;

    const int g = lane >> 3, r = lane & 7;
    const int arow_off = ((g >> 1) ? 8 : 0) + r;   // A (trans, x4)
    const int acol_off = (g & 1) ? 8 : 0;
    const int brow_off = ((g & 1) ? 8 : 0) + r;    // B (trans, x2)

    // hoisted base pointers; row stride = Hq*Dq = Hq*Mq = 512 floats
    const float* kp = Kp + ((size_t)(b * Nq + n0) * Hq + h) * Dq;
    const float* vp = Vp + ((size_t)(b * Nq + n0) * Hq + h) * Mq;
    const int nrow = tid >> 4, c4 = tid & 15;   // 4 staging jobs/chunk: n = i*16+nrow

    float4 kreg[4], vreg[4];
    // prefetch chunk 0
    #pragma unroll
    for (int i = 0; i < 4; i++) {
        const int n = i * 16 + nrow;
        kreg[i] = *(const float4*)(kp + (size_t)n * 512 + c4 * 4);
        vreg[i] = *(const float4*)(vp + (size_t)n * 512 + c4 * 4);
    }

    float4 acc[4];
    #pragma unroll
    for (int j = 0; j < 4; j++) acc[j] = make_float4(0.f, 0.f, 0.f, 0.f);
    float4 accK = make_float4(0.f, 0.f, 0.f, 0.f);   // Ksum accumulator (warps 0-3)

    const int d0 = 16 * strip;
    #pragma unroll
    for (int c = 0; c < 2; c++) {
        const int buf = c;
        // convert + STS current chunk from regs
        #pragma unroll
        for (int i = 0; i < 4; i++) {
            const int n = i * 16 + nrow;
            uint2 ku, vu;
            ku.x = pack_h2(fmap(kreg[i].x), fmap(kreg[i].y));
            ku.y = pack_h2(fmap(kreg[i].z), fmap(kreg[i].w));
            *(uint2*)&Ksm[buf][n][c4 * 4] = ku;
            vu.x = pack_h2(vreg[i].x, vreg[i].y);
            vu.y = pack_h2(vreg[i].z, vreg[i].w);
            *(uint2*)&Vsm[buf][n][c4 * 4] = vu;
        }
        // prefetch next chunk — LDG in flight during the MMA below
        if (c == 0) {
            #pragma unroll
            for (int i = 0; i < 4; i++) {
                const int n = 64 + i * 16 + nrow;
                kreg[i] = *(const float4*)(kp + (size_t)n * 512 + c4 * 4);
                vreg[i] = *(const float4*)(vp + (size_t)n * 512 + c4 * 4);
            }
        }
        __syncthreads();

        const unsigned Kbase = (unsigned)__cvta_generic_to_shared(&Ksm[buf][0][0]);
        const unsigned Vbase = (unsigned)__cvta_generic_to_shared(&Vsm[buf][0][0]);
        #pragma unroll
        for (int ks = 0; ks < 4; ks++) {
            const int k0 = ks * 16;
            unsigned a0, a1, a2, a3;
            const unsigned aaddr = Kbase +
                ((unsigned)((k0 + arow_off) * P2 + d0 + acol_off)) * 2u;
            ldm_x4t(a0, a1, a2, a3, aaddr);
            if (w < 4)   // Ksum = K'^T @ ones
                mma_fp16(accK, a0, a1, a2, a3, ONESH2, ONESH2);
            #pragma unroll
            for (int j = 0; j < 4; j++) {
                const int m0 = 8 * (jt0 + j);
                unsigned b0, b1;
                const unsigned baddr = Vbase +
                    ((unsigned)((k0 + brow_off) * P2 + m0)) * 2u;
                ldm_x2t(b0, b1, baddr);
                mma_fp16(acc[j], a0, a1, a2, a3, b0, b1);
            }
        }
    }

    // epilogue: write partial KV (block exclusively owns [seg][bh])
    float* kv = g_KVp + ((size_t)seg * BH + bh) * Dq * Mq;
    const int d = d0 + gid;
    #pragma unroll
    for (int j = 0; j < 4; j++) {
        const int m = 8 * (jt0 + j) + 2 * tig;
        *(float2*)(kv + (size_t)d * Mq + m)       = make_float2(acc[j].x, acc[j].y);
        *(float2*)(kv + (size_t)(d + 8) * Mq + m) = make_float2(acc[j].z, acc[j].w);
    }
    if (w < 4 && tig == 0) {   // col 0 of the ones-MMA = Ksum strip
        float* kss = g_Ksp + ((size_t)seg * BH + bh) * Dq;
        kss[d0 + gid]     = accK.x;
        kss[d0 + gid + 8] = accK.z;
    }
}

// ============ reduce: sum SEG partials ============
__global__ void __launch_bounds__(256) reduce_kernel() {
    const int i = blockIdx.x * 256 + threadIdx.x;
    if (i < BH * Dq * Mq) {
        float s = 0.0f;
        #pragma unroll
        for (int sg = 0; sg < SEG; sg++) s += g_KVp[(size_t)sg * BH * Dq * Mq + i];
        g_KV[i] = s;
    }
    if (i < BH * Dq) {
        float s = 0.0f;
        #pragma unroll
        for (int sg = 0; sg < SEG; sg++) s += g_Ksp[sg * BH * Dq + i];
        g_Ksum[i] = s;
    }
}

// ============ pass2: out = Z * fmap(Q) @ KV ============
// grid (64, H, B) = 2048 blocks, 256 thr (8 warps), min 4 blocks/SM. 64 n-rows/block;
// inter-block wave overlap hides staging latency (13.8 blocks/SM supply).
// Warp w: n-strip = w&3 (16 rows), m j-tiles 4*(w>>2)..+3.
// Z folded into MMA with B = Ksum fragments.
__global__ void __launch_bounds__(256, 4) pass2_kernel(const float* __restrict__ Qp,
                                                       float* __restrict__ Op) {
    __shared__ __align__(16) __half Qsm[64][P2];    // [n][d]
    __shared__ __align__(16) __half KVsm[64][P2];   // [d][m]
    __shared__ float Kss[64];

    const int b = blockIdx.z, h = blockIdx.y;
    const int bh = b * Hq + h;
    const int n0 = blockIdx.x * 64;
    const int tid = threadIdx.x;
    const int w = tid >> 5, lane = tid & 31;
    const int gid = lane >> 2, tig = lane & 3;
    const int strip = w & 3;
    const int jt0 = (w >> 2) * 4;

    const unsigned Qbase  = (unsigned)__cvta_generic_to_shared(&Qsm[0][0]);
    const unsigned KVbase = (unsigned)__cvta_generic_to_shared(&KVsm[0][0]);
    const int g = lane >> 3, r = lane & 7;
    const int arow_off = ((g & 1) ? 8 : 0) + r;    // A (non-trans, x4)
    const int acol_off = (g >> 1) ? 8 : 0;
    const int brow_off = ((g & 1) ? 8 : 0) + r;    // B (trans, x2)

    const float* kvg = g_KV + (size_t)bh * Dq * Mq;
    const float* qp  = Qp + ((size_t)(b * Nq + n0) * Hq + h) * Dq;
    const int nrow = tid >> 4, c4 = tid & 15;

    // staging: Q (4 jobs) + KV (4 jobs, L2-resident) + Ksum
    #pragma unroll
    for (int it = 0; it < 4; it++) {
        const int rr = it * 16 + nrow;
        const float4 q = *(const float4*)(qp + (size_t)rr * 512 + c4 * 4);
        uint2 qu;
        qu.x = pack_h2(fmap(q.x), fmap(q.y));
        qu.y = pack_h2(fmap(q.z), fmap(q.w));
        *(uint2*)&Qsm[rr][c4 * 4] = qu;

        const float4 t = *(const float4*)(kvg + (size_t)rr * Mq + c4 * 4);
        uint2 tu;
        tu.x = pack_h2(t.x, t.y);
        tu.y = pack_h2(t.z, t.w);
        *(uint2*)&KVsm[rr][c4 * 4] = tu;
    }
    if (tid < 64) Kss[tid] = g_Ksum[bh * Dq + tid];
    __syncthreads();

    float4 acc[4];
    #pragma unroll
    for (int j = 0; j < 4; j++) acc[j] = make_float4(0.f, 0.f, 0.f, 0.f);
    float4 accZ = make_float4(0.f, 0.f, 0.f, 0.f);

    const int nr0 = 16 * strip;
    #pragma unroll
    for (int ks = 0; ks < 4; ks++) {
        const int k0 = ks * 16;
        unsigned a0, a1, a2, a3;
        const unsigned aaddr = Qbase +
            ((unsigned)((nr0 + arow_off) * P2 + k0 + acol_off)) * 2u;
        ldm_x4(a0, a1, a2, a3, aaddr);
        // Z fragment: B[k][n] = Kss[k] broadcast over n
        const unsigned zb0 = pack_h2(Kss[k0 + 2 * tig],     Kss[k0 + 2 * tig + 1]);
        const unsigned zb1 = pack_h2(Kss[k0 + 2 * tig + 8], Kss[k0 + 2 * tig + 9]);
        mma_fp16(accZ, a0, a1, a2, a3, zb0, zb1);
        #pragma unroll
        for (int j = 0; j < 4; j++) {
            const int m0 = 8 * (jt0 + j);
            unsigned b0, b1;
            const unsigned baddr = KVbase +
                ((unsigned)((k0 + brow_off) * P2 + m0)) * 2u;
            ldm_x2t(b0, b1, baddr);
            mma_fp16(acc[j], a0, a1, a2, a3, b0, b1);
        }
    }

    // per-lane normalizers from the Z-tile
    const float z0 = 1.0f / (accZ.x + 1e-6f);
    const float z1 = 1.0f / (accZ.z + 1e-6f);

    // epilogue: scale by Z, store
    const int row = nr0 + gid;
    float* op0 = Op + ((size_t)(b * Nq + n0 + row) * Hq + h) * Mq;
    float* op1 = op0 + (size_t)8 * Hq * Mq;
    #pragma unroll
    for (int j = 0; j < 4; j++) {
        const int m = 8 * (jt0 + j) + 2 * tig;
        *(float2*)(op0 + m) = make_float2(acc[j].x * z0, acc[j].y * z0);
        *(float2*)(op1 + m) = make_float2(acc[j].z * z1, acc[j].w * z1);
    }
}

extern "C" void kernel_launch(void* const* d_in, const int* in_sizes, int n_in,
                              void* d_out, int out_size) {
    const float* Q = (const float*)d_in[0];
    const float* K = (const float*)d_in[1];
    const float* V = (const float*)d_in[2];
    float* out = (float*)d_out;

    pass1_kernel<<<dim3(SEG, Hq, Bq), 256>>>(K, V);
    reduce_kernel<<<512, 256>>>();
    pass2_kernel<<<dim3(64, Hq, Bq), 256>>>(Q, out);
}